// round 7
// baseline (speedup 1.0000x reference)
#include <cuda_runtime.h>

#define N 8192
#define ROWS_PER_BLK 64
#define COLS_PER_BLK 1024
#define CB 8      /* column tiles: 8192/1024 */
#define RB 128    /* row tiles:    8192/64   */
#define THREADS 256
#define NGROUP 8  /* column groups of 1024 */

// Scratch (no device allocation allowed -> __device__ globals)
__device__ float g_rowpart[CB * N];     // [cb][row]  partial row sums (256 KB)
__device__ float g_colpart[RB * N];     // [rb][col]  partial col sums (4 MiB)
__device__ float g_groupsum[NGROUP];
__device__ int   g_cnt_group[NGROUP];   // zero-init; self-resetting
__device__ int   g_cnt_final;           // zero-init; self-resetting

// ---------------------------------------------------------------------------
// Finish column group g (columns [g*1024, (g+1)*1024)): fold 128 colparts +
// 8 rowparts per column, |.|, deterministic block reduce -> g_groupsum[g].
// The globally-last finisher folds the 8 group sums -> out, resets counters.
// ---------------------------------------------------------------------------
__device__ __forceinline__ void finish_group(int g, int t, float* out)
{
    __threadfence();   // acquire: make producer writes visible

    // Thread t owns columns g*1024 + 4t .. +3  (256 threads x 4 = 1024)
    const float4* cp = reinterpret_cast<const float4*>(g_colpart + g * 1024) + t;
    float4 cs = make_float4(0.f, 0.f, 0.f, 0.f);
    #pragma unroll 8
    for (int rb = 0; rb < RB; ++rb) {
        float4 a = cp[(size_t)rb * (N / 4)];
        cs.x += a.x; cs.y += a.y; cs.z += a.z; cs.w += a.w;
    }

    float4 rs = make_float4(0.f, 0.f, 0.f, 0.f);
    #pragma unroll
    for (int cb = 0; cb < CB; ++cb) {
        float4 a = reinterpret_cast<const float4*>(g_rowpart + cb * N + g * 1024)[t];
        rs.x += a.x; rs.y += a.y; rs.z += a.z; rs.w += a.w;
    }

    float v = (fabsf(rs.x - cs.x) + fabsf(rs.y - cs.y))
            + (fabsf(rs.z - cs.z) + fabsf(rs.w - cs.w));
    v += __shfl_xor_sync(0xffffffffu, v, 16);
    v += __shfl_xor_sync(0xffffffffu, v, 8);
    v += __shfl_xor_sync(0xffffffffu, v, 4);
    v += __shfl_xor_sync(0xffffffffu, v, 2);
    v += __shfl_xor_sync(0xffffffffu, v, 1);

    __shared__ float sw[8];
    __shared__ int s_fin;
    if ((t & 31) == 0) sw[t >> 5] = v;
    __syncthreads();

    if (t == 0) {
        float w = ((sw[0] + sw[1]) + (sw[2] + sw[3]))
                + ((sw[4] + sw[5]) + (sw[6] + sw[7]));
        g_groupsum[g] = w;
        __threadfence();
        s_fin = (atomicAdd(&g_cnt_final, 1) == NGROUP - 1);
    }
    __syncthreads();

    if (s_fin) {
        __threadfence();
        if (t < 32) {
            float v2 = (t < NGROUP) ? g_groupsum[t] : 0.f;
            v2 += __shfl_xor_sync(0xffffffffu, v2, 4);
            v2 += __shfl_xor_sync(0xffffffffu, v2, 2);
            v2 += __shfl_xor_sync(0xffffffffu, v2, 1);
            if (t == 0) {
                out[0] = v2;
                g_cnt_final = 0;                 // reset for next graph replay
                #pragma unroll
                for (int k = 0; k < NGROUP; ++k) g_cnt_group[k] = 0;
            }
        }
    }
    __syncthreads();
}

// ---------------------------------------------------------------------------
// Single fused kernel: one block per 64x1024 tile -> 1024 blocks. Streaming
// single read of the 256 MiB matrix (proven loop). After writing its
// partials, each block bumps 2 group counters; the 256th arrival per group
// runs the group finisher in-kernel (no second launch).
// ---------------------------------------------------------------------------
__global__ void __launch_bounds__(THREADS, 7)
tile_kernel(const float* __restrict__ flow, float* __restrict__ out)
{
    const int cb   = blockIdx.x;          // 0..7
    const int rb   = blockIdx.y;          // 0..127
    const int t    = threadIdx.x;         // 0..255
    const int warp = t >> 5;
    const int lane = t & 31;
    const int row0 = rb * ROWS_PER_BLK;
    const int col0 = cb * COLS_PER_BLK;

    __shared__ float s_row[ROWS_PER_BLK][32];   // [row][warp*4 + sublane] 8 KB

    float4 c0 = make_float4(0.f, 0.f, 0.f, 0.f);

    const float4* base = reinterpret_cast<const float4*>(flow)
                         + (size_t)row0 * (N / 4) + (col0 / 4);

    #pragma unroll 4
    for (int r = 0; r < ROWS_PER_BLK; ++r) {
        float4 a = __ldcs(base + (size_t)r * (N / 4) + t);   // streaming

        c0.x += a.x; c0.y += a.y; c0.z += a.z; c0.w += a.w;

        // partial row reduce: 32 lanes -> 4 partials (3 shuffles)
        float s = (a.x + a.y) + (a.z + a.w);
        s += __shfl_xor_sync(0xffffffffu, s, 16);
        s += __shfl_xor_sync(0xffffffffu, s, 8);
        s += __shfl_xor_sync(0xffffffffu, s, 4);
        if (lane < 4) s_row[r][warp * 4 + lane] = s;
    }

    // Column partials: unique writer per (rb, col) -> plain store, no atomics
    reinterpret_cast<float4*>(g_colpart + (size_t)rb * N + col0)[t] = c0;

    __syncthreads();

    // Row fold: 4 threads per row (aligned 4-lane groups), 8 values each.
    {
        const int r = t >> 2;          // 0..63
        const int j = (t & 3) * 8;     // 0,8,16,24
        float s = ((s_row[r][j]     + s_row[r][j + 1]) +
                   (s_row[r][j + 2] + s_row[r][j + 3])) +
                  ((s_row[r][j + 4] + s_row[r][j + 5]) +
                   (s_row[r][j + 6] + s_row[r][j + 7]));
        s += __shfl_xor_sync(0xffffffffu, s, 2);
        s += __shfl_xor_sync(0xffffffffu, s, 1);
        if ((t & 3) == 0) g_rowpart[cb * N + row0 + r] = s;
    }

    // ---- fused epilogue gating ----
    // Group g needs: 128 colpart blocks (cb==g) + 128 rowpart blocks
    // (rb>>4==g) -> counter target 256. Each block increments both counters.
    __threadfence();   // release: partials visible before counter bump

    const int rg = rb >> 4;            // rowpart group this block feeds
    __shared__ int s_f1, s_f2;
    if (t == 0) {
        s_f1 = (atomicAdd(&g_cnt_group[cb], 1) == 255);
        s_f2 = (atomicAdd(&g_cnt_group[rg], 1) == 255);
    }
    __syncthreads();

    if (s_f1) finish_group(cb, t, out);
    if (s_f2) finish_group(rg, t, out);
}

extern "C" void kernel_launch(void* const* d_in, const int* in_sizes, int n_in,
                              void* d_out, int out_size)
{
    (void)in_sizes; (void)n_in; (void)out_size;
    const float* flow = (const float*)d_in[0];
    float* out = (float*)d_out;

    tile_kernel<<<dim3(CB, RB), THREADS>>>(flow, out);
}

// round 8
// speedup vs baseline: 1.6241x; 1.6241x over previous
#include <cuda_runtime.h>

#define N 8192
#define ROWS_PER_BLK 64
#define COLS_PER_BLK 1024
#define CB 8      /* column tiles: 8192/1024 */
#define RB 128    /* row tiles:    8192/64   */
#define THREADS 256
#define CHUNKS 16 /* combine chunks over RB (8 rb each) */

// Scratch (no device allocation allowed -> __device__ globals)
__device__ float g_rowpart[CB * N];       // [cb][row]  partial row sums (256 KB)
__device__ float g_colpart[RB * N];       // [rb][col]  partial col sums (4 MiB)
__device__ float g_cpart2[CHUNKS * N];    // folded col partials (512 KB)
__device__ float g_blocksum[32];
__device__ int   g_cnt_final;             // zero-init; self-resetting

// ---------------------------------------------------------------------------
// Pass 1 (identical to R6's proven 42us kernel): one block per 64x1024 tile
// -> 1024 blocks. Streaming single read of the 256 MiB matrix.
// ---------------------------------------------------------------------------
__global__ void __launch_bounds__(THREADS)
tile_kernel(const float* __restrict__ flow)
{
    const int cb   = blockIdx.x;          // 0..7
    const int rb   = blockIdx.y;          // 0..127
    const int t    = threadIdx.x;         // 0..255
    const int warp = t >> 5;
    const int lane = t & 31;
    const int row0 = rb * ROWS_PER_BLK;
    const int col0 = cb * COLS_PER_BLK;

    __shared__ float s_row[ROWS_PER_BLK][32];   // [row][warp*4 + sublane] 8 KB

    float4 c0 = make_float4(0.f, 0.f, 0.f, 0.f);

    const float4* base = reinterpret_cast<const float4*>(flow)
                         + (size_t)row0 * (N / 4) + (col0 / 4);

    #pragma unroll 4
    for (int r = 0; r < ROWS_PER_BLK; ++r) {
        float4 a = __ldcs(base + (size_t)r * (N / 4) + t);   // streaming

        c0.x += a.x; c0.y += a.y; c0.z += a.z; c0.w += a.w;

        // partial row reduce: 32 lanes -> 4 partials (3 shuffles)
        float s = (a.x + a.y) + (a.z + a.w);
        s += __shfl_xor_sync(0xffffffffu, s, 16);
        s += __shfl_xor_sync(0xffffffffu, s, 8);
        s += __shfl_xor_sync(0xffffffffu, s, 4);
        if (lane < 4) s_row[r][warp * 4 + lane] = s;
    }

    // Column partials: unique writer per (rb, col) -> plain store, no atomics
    reinterpret_cast<float4*>(g_colpart + (size_t)rb * N + col0)[t] = c0;

    __syncthreads();

    // Row fold: 4 threads per row (aligned 4-lane groups), 8 values each.
    {
        const int r = t >> 2;          // 0..63
        const int j = (t & 3) * 8;     // 0,8,16,24
        float s = ((s_row[r][j]     + s_row[r][j + 1]) +
                   (s_row[r][j + 2] + s_row[r][j + 3])) +
                  ((s_row[r][j + 4] + s_row[r][j + 5]) +
                   (s_row[r][j + 6] + s_row[r][j + 7]));
        s += __shfl_xor_sync(0xffffffffu, s, 2);
        s += __shfl_xor_sync(0xffffffffu, s, 1);
        if ((t & 3) == 0) g_rowpart[cb * N + row0 + r] = s;
    }
}

// ---------------------------------------------------------------------------
// Pass 2: 512 blocks = (32 col groups) x (16 rb-chunks). Each block folds
// 8 rb-partials for its 256 columns (8 independent coalesced loads/thread).
// ---------------------------------------------------------------------------
__global__ void __launch_bounds__(256)
combine_kernel(void)
{
    const int t  = threadIdx.x;
    const int bx = blockIdx.x;     // column group 0..31
    const int by = blockIdx.y;     // rb chunk     0..15
    const int i  = bx * 256 + t;

    float cs = 0.f;
    #pragma unroll
    for (int j = 0; j < RB / CHUNKS; ++j)
        cs += g_colpart[(size_t)(by * (RB / CHUNKS) + j) * N + i];

    g_cpart2[by * N + i] = cs;
}

// ---------------------------------------------------------------------------
// Pass 3: 32 blocks. Per column fold 16 chunk partials + 8 row partials
// (L2-hot), |.|, block reduce; counter-gated last block folds 32 scalars
// -> out and resets the counter (graph-replay safe, deterministic).
// ---------------------------------------------------------------------------
__global__ void __launch_bounds__(256)
final_kernel(float* __restrict__ out)
{
    const int t = threadIdx.x;
    const int i = blockIdx.x * 256 + t;

    float cs = 0.f;
    #pragma unroll
    for (int p = 0; p < CHUNKS; ++p) cs += g_cpart2[p * N + i];

    float rs = 0.f;
    #pragma unroll
    for (int cb = 0; cb < CB; ++cb) rs += g_rowpart[cb * N + i];

    float v = fabsf(rs - cs);
    v += __shfl_xor_sync(0xffffffffu, v, 16);
    v += __shfl_xor_sync(0xffffffffu, v, 8);
    v += __shfl_xor_sync(0xffffffffu, v, 4);
    v += __shfl_xor_sync(0xffffffffu, v, 2);
    v += __shfl_xor_sync(0xffffffffu, v, 1);

    __shared__ float sw[8];
    if ((t & 31) == 0) sw[t >> 5] = v;
    __syncthreads();

    __shared__ int s_fin;
    if (t == 0) {
        float w = ((sw[0] + sw[1]) + (sw[2] + sw[3]))
                + ((sw[4] + sw[5]) + (sw[6] + sw[7]));
        g_blocksum[blockIdx.x] = w;
        __threadfence();
        s_fin = (atomicAdd(&g_cnt_final, 1) == 31);
    }
    __syncthreads();
    if (!s_fin) return;
    __threadfence();

    if (t < 32) {
        float v2 = g_blocksum[t];
        v2 += __shfl_xor_sync(0xffffffffu, v2, 16);
        v2 += __shfl_xor_sync(0xffffffffu, v2, 8);
        v2 += __shfl_xor_sync(0xffffffffu, v2, 4);
        v2 += __shfl_xor_sync(0xffffffffu, v2, 2);
        v2 += __shfl_xor_sync(0xffffffffu, v2, 1);
        if (t == 0) {
            out[0] = v2;
            g_cnt_final = 0;   // reset for next graph replay
        }
    }
}

extern "C" void kernel_launch(void* const* d_in, const int* in_sizes, int n_in,
                              void* d_out, int out_size)
{
    (void)in_sizes; (void)n_in; (void)out_size;
    const float* flow = (const float*)d_in[0];
    float* out = (float*)d_out;

    tile_kernel<<<dim3(CB, RB), THREADS>>>(flow);
    combine_kernel<<<dim3(32, CHUNKS), 256>>>();
    final_kernel<<<32, 256>>>(out);
}